// round 1
// baseline (speedup 1.0000x reference)
#include <cuda_runtime.h>
#include <math.h>
#include <math_constants.h>

#define BATCH  4
#define SEQ    2048
#define DMODEL 1024
#define NHEADS 16
#define DHEAD  64

// Scratch (device globals — allocation-free per harness rules)
__device__ float g_q[(size_t)BATCH * NHEADS * SEQ * DHEAD];
__device__ float g_k[(size_t)BATCH * NHEADS * SEQ * DHEAD];
__device__ float g_v[(size_t)BATCH * NHEADS * SEQ * DHEAD];
__device__ float g_attn[(size_t)BATCH * SEQ * DMODEL];

// ---------------------------------------------------------------------------
// NT SGEMM: C[m,n] = sum_k A[m,k] * W[n,k] + bias[n]
// A: [M,K] row-major, W: [N,K] row-major. 128x128x8 tile, 256 thr, 8x8 micro.
// MODE 0: A = x input, epilogue scatters into g_q/g_k/g_v ([b,h,s,d]).
// MODE 1: A = g_attn (param ignored), epilogue writes C[m*N+n].
// ---------------------------------------------------------------------------
template <int MODE>
__global__ __launch_bounds__(256) void sgemm_nt(
    const float* __restrict__ A, const float* __restrict__ W,
    const float* __restrict__ bias, float* __restrict__ C,
    int M, int N, int K)
{
    __shared__ float As[8][128];
    __shared__ float Bs[8][128];

    const int tid = threadIdx.x;
    const int tx = tid & 15;         // 0..15 -> N microtile
    const int ty = tid >> 4;         // 0..15 -> M microtile
    const int bm = blockIdx.y;
    const int bn = blockIdx.x;

    const float* Ag   = (MODE == 1) ? g_attn : A;
    const float* Aptr = Ag + (size_t)bm * 128 * K;
    const float* Wptr = W  + (size_t)bn * 128 * K;

    const int loadRow = tid >> 1;        // 0..127
    const int loadCol = (tid & 1) << 2;  // 0 or 4

    float acc[8][8] = {};

    for (int k0 = 0; k0 < K; k0 += 8) {
        float4 a4 = *(const float4*)(Aptr + (size_t)loadRow * K + k0 + loadCol);
        float4 b4 = *(const float4*)(Wptr + (size_t)loadRow * K + k0 + loadCol);
        __syncthreads();   // previous iteration's compute done with smem
        As[loadCol + 0][loadRow] = a4.x;
        As[loadCol + 1][loadRow] = a4.y;
        As[loadCol + 2][loadRow] = a4.z;
        As[loadCol + 3][loadRow] = a4.w;
        Bs[loadCol + 0][loadRow] = b4.x;
        Bs[loadCol + 1][loadRow] = b4.y;
        Bs[loadCol + 2][loadRow] = b4.z;
        Bs[loadCol + 3][loadRow] = b4.w;
        __syncthreads();

        #pragma unroll
        for (int kk = 0; kk < 8; kk++) {
            float af[8], bf[8];
            *(float4*)(af)     = *(const float4*)&As[kk][ty * 8];
            *(float4*)(af + 4) = *(const float4*)&As[kk][ty * 8 + 4];
            *(float4*)(bf)     = *(const float4*)&Bs[kk][tx * 8];
            *(float4*)(bf + 4) = *(const float4*)&Bs[kk][tx * 8 + 4];
            #pragma unroll
            for (int i = 0; i < 8; i++)
                #pragma unroll
                for (int j = 0; j < 8; j++)
                    acc[i][j] = fmaf(af[i], bf[j], acc[i][j]);
        }
    }

    // Epilogue
    #pragma unroll
    for (int i = 0; i < 8; i++) {
        const int m = bm * 128 + ty * 8 + i;
        if (MODE == 0) {
            const int b = m >> 11;          // /2048
            const int s = m & 2047;
            #pragma unroll
            for (int j = 0; j < 8; j++) {
                const int n = bn * 128 + tx * 8 + j;
                const float v = acc[i][j] + bias[n];
                const int part = n >> 10;   // 0=q,1=k,2=v
                const int hd   = n & 1023;
                const int h    = hd >> 6;
                const int d    = hd & 63;
                float* dst = (part == 0) ? g_q : (part == 1) ? g_k : g_v;
                dst[(((size_t)(b * NHEADS + h)) * SEQ + s) * DHEAD + d] = v;
            }
        } else {
            #pragma unroll
            for (int j = 0; j < 8; j++) {
                const int n = bn * 128 + tx * 8 + j;
                C[(size_t)m * N + n] = acc[i][j] + bias[n];
            }
        }
    }
}

// ---------------------------------------------------------------------------
// Flash attention: one CTA per (b, h, q-tile of 64). Online softmax.
// Smem: Qs[d][i], KPs[d][j] (reused as P[i][j]), Vs[j][dd], stride 68.
// 256 threads, each owns a 4x4 microtile of the 64x64 tile.
// ---------------------------------------------------------------------------
#define FSTRIDE 68   // 64 + 4 pad: float4-aligned rows, low bank conflicts

__global__ __launch_bounds__(256) void flash_attn(const int* __restrict__ maskFlag)
{
    extern __shared__ float sm[];
    float* Qs  = sm;                   // [64][FSTRIDE]  (transposed: [d][i])
    float* KPs = sm + 64 * FSTRIDE;    // K: [d][j], then reused as P: [i][j]
    float* Vs  = sm + 2 * 64 * FSTRIDE;// [j][dd]

    const int tid = threadIdx.x;
    const int tx  = tid & 15;
    const int ty  = tid >> 4;
    const int qt  = (int)gridDim.x - 1 - (int)blockIdx.x;  // heavy tiles first
    const int h   = blockIdx.y;
    const int b   = blockIdx.z;
    const int causal = maskFlag[0];

    const size_t bhoff = (size_t)(b * NHEADS + h) * SEQ * DHEAD;
    const float* Qg = g_q + bhoff + (size_t)qt * 64 * DHEAD;
    const float* Kg = g_k + bhoff;
    const float* Vg = g_v + bhoff;

    // Load Q tile transposed: Qs[d][i]
    for (int t = tid; t < 64 * 16; t += 256) {
        const int r = t >> 4;
        const int c = (t & 15) << 2;
        float4 v = *(const float4*)(Qg + r * 64 + c);
        Qs[(c + 0) * FSTRIDE + r] = v.x;
        Qs[(c + 1) * FSTRIDE + r] = v.y;
        Qs[(c + 2) * FSTRIDE + r] = v.z;
        Qs[(c + 3) * FSTRIDE + r] = v.w;
    }

    float m_i[4], l_i[4], o[4][4];
    #pragma unroll
    for (int i = 0; i < 4; i++) {
        m_i[i] = -CUDART_INF_F;
        l_i[i] = 0.0f;
        #pragma unroll
        for (int c = 0; c < 4; c++) o[i][c] = 0.0f;
    }

    const int ktEnd = causal ? qt : (SEQ / 64 - 1);

    for (int kt = 0; kt <= ktEnd; kt++) {
        __syncthreads();  // previous iter done with KPs/Vs (also covers Q load)
        const float* Kt = Kg + (size_t)kt * 64 * DHEAD;
        const float* Vt = Vg + (size_t)kt * 64 * DHEAD;
        for (int t = tid; t < 64 * 16; t += 256) {
            const int r = t >> 4;
            const int c = (t & 15) << 2;
            float4 kv = *(const float4*)(Kt + r * 64 + c);
            KPs[(c + 0) * FSTRIDE + r] = kv.x;
            KPs[(c + 1) * FSTRIDE + r] = kv.y;
            KPs[(c + 2) * FSTRIDE + r] = kv.z;
            KPs[(c + 3) * FSTRIDE + r] = kv.w;
            float4 vv = *(const float4*)(Vt + r * 64 + c);
            *(float4*)&Vs[r * FSTRIDE + c] = vv;
        }
        __syncthreads();

        // S = Q K^T  (reduce over d)
        float s[4][4] = {};
        #pragma unroll 8
        for (int d = 0; d < 64; d++) {
            float qf[4], kf[4];
            *(float4*)qf = *(const float4*)&Qs[d * FSTRIDE + ty * 4];
            *(float4*)kf = *(const float4*)&KPs[d * FSTRIDE + tx * 4];
            #pragma unroll
            for (int i = 0; i < 4; i++)
                #pragma unroll
                for (int j = 0; j < 4; j++)
                    s[i][j] = fmaf(qf[i], kf[j], s[i][j]);
        }

        // Scale + causal mask (diagonal tile only)
        #pragma unroll
        for (int i = 0; i < 4; i++)
            #pragma unroll
            for (int j = 0; j < 4; j++)
                s[i][j] *= 0.125f;  // 1/sqrt(64)
        if (causal && kt == qt) {
            #pragma unroll
            for (int i = 0; i < 4; i++)
                #pragma unroll
                for (int j = 0; j < 4; j++)
                    if (tx * 4 + j > ty * 4 + i) s[i][j] = -CUDART_INF_F;
        }

        // Online softmax (row groups = 16 lanes sharing ty; shfl width 16)
        float p[4][4];
        #pragma unroll
        for (int i = 0; i < 4; i++) {
            float rm = s[i][0];
            #pragma unroll
            for (int j = 1; j < 4; j++) rm = fmaxf(rm, s[i][j]);
            #pragma unroll
            for (int off = 8; off >= 1; off >>= 1)
                rm = fmaxf(rm, __shfl_xor_sync(0xffffffffu, rm, off, 16));
            const float mnew = fmaxf(m_i[i], rm);
            const float alpha = __expf(m_i[i] - mnew);
            float rs = 0.0f;
            #pragma unroll
            for (int j = 0; j < 4; j++) {
                p[i][j] = __expf(s[i][j] - mnew);
                rs += p[i][j];
            }
            #pragma unroll
            for (int off = 8; off >= 1; off >>= 1)
                rs += __shfl_xor_sync(0xffffffffu, rs, off, 16);
            l_i[i] = l_i[i] * alpha + rs;
            m_i[i] = mnew;
            #pragma unroll
            for (int c = 0; c < 4; c++) o[i][c] *= alpha;
        }

        __syncthreads();  // everyone done reading KPs as K
        // Write P into KPs as [i][j]
        #pragma unroll
        for (int i = 0; i < 4; i++)
            #pragma unroll
            for (int j = 0; j < 4; j++)
                KPs[(ty * 4 + i) * FSTRIDE + tx * 4 + j] = p[i][j];
        __syncthreads();

        // O += P V  (reduce over j)
        #pragma unroll 8
        for (int j = 0; j < 64; j++) {
            float pf[4], vf[4];
            #pragma unroll
            for (int i = 0; i < 4; i++) pf[i] = KPs[(ty * 4 + i) * FSTRIDE + j];
            *(float4*)vf = *(const float4*)&Vs[j * FSTRIDE + tx * 4];
            #pragma unroll
            for (int i = 0; i < 4; i++)
                #pragma unroll
                for (int c = 0; c < 4; c++)
                    o[i][c] = fmaf(pf[i], vf[c], o[i][c]);
        }
    }

    // Epilogue: normalize and store to [b, s, h*64+dd]
    #pragma unroll
    for (int i = 0; i < 4; i++) {
        const float inv = 1.0f / l_i[i];
        const int srow = qt * 64 + ty * 4 + i;
        float* dst = g_attn + ((size_t)b * SEQ + srow) * DMODEL + h * 64 + tx * 4;
        float4 v;
        v.x = o[i][0] * inv;
        v.y = o[i][1] * inv;
        v.z = o[i][2] * inv;
        v.w = o[i][3] * inv;
        *(float4*)dst = v;
    }
}

// ---------------------------------------------------------------------------
extern "C" void kernel_launch(void* const* d_in, const int* in_sizes, int n_in,
                              void* d_out, int out_size)
{
    const float* x    = (const float*)d_in[0];   // [4, 2048, 1024]
    const float* w1   = (const float*)d_in[1];   // [3072, 1024]
    const float* b1   = (const float*)d_in[2];   // [3072]
    const float* w2   = (const float*)d_in[3];   // [1024, 1024]
    const float* b2   = (const float*)d_in[4];   // [1024]
    const int*   msk  = (const int*)  d_in[5];   // scalar flag
    float* out = (float*)d_out;

    const int M = BATCH * SEQ;       // 8192

    // 1) QKV projection -> g_q/g_k/g_v
    sgemm_nt<0><<<dim3(3 * DMODEL / 128, M / 128), 256>>>(
        x, w1, b1, nullptr, M, 3 * DMODEL, DMODEL);

    // 2) Flash attention -> g_attn
    const int smemBytes = 3 * 64 * FSTRIDE * (int)sizeof(float);  // 52224
    cudaFuncSetAttribute(flash_attn,
                         cudaFuncAttributeMaxDynamicSharedMemorySize, smemBytes);
    flash_attn<<<dim3(SEQ / 64, NHEADS, BATCH), 256, smemBytes>>>(msk);

    // 3) Output projection -> d_out
    sgemm_nt<1><<<dim3(DMODEL / 128, M / 128), 256>>>(
        nullptr, w2, b2, out, M, DMODEL, DMODEL);
}

// round 3
// speedup vs baseline: 4.2256x; 4.2256x over previous
#include <cuda_runtime.h>
#include <math.h>
#include <math_constants.h>
#include <cstdint>

#define BATCH  4
#define SEQ    2048
#define DMODEL 1024
#define NHEADS 16
#define DHEAD  64

// Scratch (device globals — allocation-free per harness rules)
__device__ float g_q[(size_t)BATCH * NHEADS * SEQ * DHEAD];
__device__ float g_k[(size_t)BATCH * NHEADS * SEQ * DHEAD];
__device__ float g_v[(size_t)BATCH * NHEADS * SEQ * DHEAD];
__device__ float g_attn[(size_t)BATCH * SEQ * DMODEL];

// ---------------------------------------------------------------------------
// helpers
// ---------------------------------------------------------------------------
__device__ __forceinline__ float tf32r(float x) {
    float r;
    asm("cvt.rna.tf32.f32 %0, %1;" : "=f"(r) : "f"(x));
    return r;
}

__device__ __forceinline__ uint32_t fbits(float x) { return __float_as_uint(x); }

// D = A(16x8 tf32, row) * B(8x8 tf32, col) + D   (f32 accum)
__device__ __forceinline__ void mma_tf32(float c[4],
                                         uint32_t a0, uint32_t a1,
                                         uint32_t a2, uint32_t a3,
                                         uint32_t b0, uint32_t b1) {
    asm volatile(
        "mma.sync.aligned.m16n8k8.row.col.f32.tf32.tf32.f32 "
        "{%0,%1,%2,%3}, {%4,%5,%6,%7}, {%8,%9}, {%0,%1,%2,%3};"
        : "+f"(c[0]), "+f"(c[1]), "+f"(c[2]), "+f"(c[3])
        : "r"(a0), "r"(a1), "r"(a2), "r"(a3), "r"(b0), "r"(b1));
}

// ===========================================================================
// TF32 mma.sync GEMM (NT): C[m,n] = sum_k A[m,k] * W[n,k] + bias[n]
// 128x128x16 block, 256 thr = 8 warps (2m x 4n), warptile 64x32.
// MODE 0: A = x, scatter into g_q/g_k/g_v ([b,h,s,d]).  MODE 1: A = g_attn.
// ===========================================================================
#define GBK  16
#define BKP  20    // padded smem stride (conflict-free frag loads)

template <int MODE>
__global__ __launch_bounds__(256) void gemm_mma(
    const float* __restrict__ A, const float* __restrict__ W,
    const float* __restrict__ bias, float* __restrict__ C,
    int M, int N, int K)
{
    __shared__ float As[2][128 * BKP];
    __shared__ float Bs[2][128 * BKP];

    const int tid  = threadIdx.x;
    const int lane = tid & 31;
    const int g    = lane >> 2;
    const int t    = lane & 3;
    const int wid  = tid >> 5;
    const int wm   = (wid >> 2) * 64;   // 0 / 64
    const int wn   = (wid & 3) * 32;    // 0 / 32 / 64 / 96
    const int bm   = blockIdx.y;
    const int bn   = blockIdx.x;

    const float* Ag = (MODE == 1) ? g_attn : A;
    const int lrow = tid >> 1;          // 0..127
    const int lcol = (tid & 1) * 8;     // 0 / 8
    const float* Ap = Ag + (size_t)(bm * 128 + lrow) * K + lcol;
    const float* Wp = W  + (size_t)(bn * 128 + lrow) * K + lcol;

    float acc[4][4][4];
    #pragma unroll
    for (int mt = 0; mt < 4; mt++)
        #pragma unroll
        for (int nt = 0; nt < 4; nt++)
            #pragma unroll
            for (int e = 0; e < 4; e++) acc[mt][nt][e] = 0.0f;

    // ---- prologue: stage 0 ----
    {
        float4 a0 = *(const float4*)(Ap);
        float4 a1 = *(const float4*)(Ap + 4);
        float4 b0 = *(const float4*)(Wp);
        float4 b1 = *(const float4*)(Wp + 4);
        float* as = &As[0][lrow * BKP + lcol];
        float* bs = &Bs[0][lrow * BKP + lcol];
        as[0] = tf32r(a0.x); as[1] = tf32r(a0.y); as[2] = tf32r(a0.z); as[3] = tf32r(a0.w);
        as[4] = tf32r(a1.x); as[5] = tf32r(a1.y); as[6] = tf32r(a1.z); as[7] = tf32r(a1.w);
        bs[0] = tf32r(b0.x); bs[1] = tf32r(b0.y); bs[2] = tf32r(b0.z); bs[3] = tf32r(b0.w);
        bs[4] = tf32r(b1.x); bs[5] = tf32r(b1.y); bs[6] = tf32r(b1.z); bs[7] = tf32r(b1.w);
    }
    __syncthreads();

    const int NS = K / GBK;
    for (int s = 0; s < NS; s++) {
        const int buf = s & 1;

        float4 na0, na1, nb0, nb1;
        if (s + 1 < NS) {
            const int k0 = (s + 1) * GBK;
            na0 = *(const float4*)(Ap + k0);
            na1 = *(const float4*)(Ap + k0 + 4);
            nb0 = *(const float4*)(Wp + k0);
            nb1 = *(const float4*)(Wp + k0 + 4);
        }

        #pragma unroll
        for (int kk = 0; kk < 2; kk++) {
            uint32_t af[4][4];
            #pragma unroll
            for (int mt = 0; mt < 4; mt++) {
                const float* base = &As[buf][(wm + mt * 16) * BKP + kk * 8];
                af[mt][0] = fbits(base[g * BKP + t]);
                af[mt][1] = fbits(base[(g + 8) * BKP + t]);
                af[mt][2] = fbits(base[g * BKP + t + 4]);
                af[mt][3] = fbits(base[(g + 8) * BKP + t + 4]);
            }
            #pragma unroll
            for (int nt = 0; nt < 4; nt++) {
                const float* bb = &Bs[buf][(wn + nt * 8 + g) * BKP + kk * 8];
                uint32_t b0 = fbits(bb[t]);
                uint32_t b1 = fbits(bb[t + 4]);
                #pragma unroll
                for (int mt = 0; mt < 4; mt++)
                    mma_tf32(acc[mt][nt], af[mt][0], af[mt][1], af[mt][2], af[mt][3],
                             b0, b1);
            }
        }

        if (s + 1 < NS) {
            float* as = &As[buf ^ 1][lrow * BKP + lcol];
            float* bs = &Bs[buf ^ 1][lrow * BKP + lcol];
            as[0] = tf32r(na0.x); as[1] = tf32r(na0.y); as[2] = tf32r(na0.z); as[3] = tf32r(na0.w);
            as[4] = tf32r(na1.x); as[5] = tf32r(na1.y); as[6] = tf32r(na1.z); as[7] = tf32r(na1.w);
            bs[0] = tf32r(nb0.x); bs[1] = tf32r(nb0.y); bs[2] = tf32r(nb0.z); bs[3] = tf32r(nb0.w);
            bs[4] = tf32r(nb1.x); bs[5] = tf32r(nb1.y); bs[6] = tf32r(nb1.z); bs[7] = tf32r(nb1.w);
        }
        __syncthreads();
    }

    // ---- epilogue ----
    #pragma unroll
    for (int mt = 0; mt < 4; mt++) {
        #pragma unroll
        for (int half = 0; half < 2; half++) {        // rows g / g+8
            const int m = bm * 128 + wm + mt * 16 + g + half * 8;
            const int bb_ = m >> 11;
            const int srow = m & 2047;
            #pragma unroll
            for (int nt = 0; nt < 4; nt++) {
                const int n = bn * 128 + wn + nt * 8 + 2 * t;
                float2 bv = *(const float2*)(bias + n);
                float2 v;
                v.x = acc[mt][nt][half * 2 + 0] + bv.x;
                v.y = acc[mt][nt][half * 2 + 1] + bv.y;
                if (MODE == 0) {
                    const int part = n >> 10;
                    const int hd = n & 1023;
                    const int hh = hd >> 6;
                    const int d = hd & 63;
                    float* dst = (part == 0) ? g_q : (part == 1) ? g_k : g_v;
                    *(float2*)(dst + (((size_t)(bb_ * NHEADS + hh)) * SEQ + srow) * DHEAD + d) = v;
                } else {
                    *(float2*)(C + (size_t)m * N + n) = v;
                }
            }
        }
    }
}

// ===========================================================================
// Flash attention on mma.sync TF32.
// CTA = (b, h, 64-row q-tile), 128 thr = 4 warps, warp owns 16 q-rows.
// Ks[64][68] keys x d ; Vs[64][72] keys x d ; Ps[64][68] (also Q staging).
// ===========================================================================
#define KSTR 68
#define VSTR 72
#define FLASH_SMEM ((64 * KSTR + 64 * VSTR + 64 * KSTR) * 4)

__global__ __launch_bounds__(128) void flash_mma(const int* __restrict__ maskFlag)
{
    extern __shared__ float smf[];
    float* Ks = smf;
    float* Vs = smf + 64 * KSTR;
    float* Ps = Vs + 64 * VSTR;

    const int tid  = threadIdx.x;
    const int lane = tid & 31;
    const int w    = tid >> 5;
    const int g    = lane >> 2;
    const int t    = lane & 3;
    const int qt   = (int)gridDim.x - 1 - (int)blockIdx.x;  // heavy tiles first
    const int h    = blockIdx.y;
    const int b    = blockIdx.z;
    const int causal = maskFlag[0];

    const size_t bh = (size_t)(b * NHEADS + h) * SEQ * DHEAD;
    const float* Qg = g_q + bh + (size_t)qt * 64 * DHEAD;
    const float* Kg = g_k + bh;
    const float* Vg = g_v + bh;

    // ---- stage Q (scaled by 1/8, tf32-rounded) into Ps, pull fragments ----
    for (int i = tid; i < 64 * 16; i += 128) {
        const int r = i >> 4;
        const int c4 = (i & 15) * 4;
        float4 v = *(const float4*)(Qg + r * 64 + c4);
        float* p = &Ps[r * KSTR + c4];
        p[0] = tf32r(v.x * 0.125f);
        p[1] = tf32r(v.y * 0.125f);
        p[2] = tf32r(v.z * 0.125f);
        p[3] = tf32r(v.w * 0.125f);
    }
    __syncthreads();

    uint32_t qf[8][4];
    #pragma unroll
    for (int k8 = 0; k8 < 8; k8++) {
        const float* base = &Ps[(w * 16) * KSTR + k8 * 8];
        qf[k8][0] = fbits(base[g * KSTR + t]);
        qf[k8][1] = fbits(base[(g + 8) * KSTR + t]);
        qf[k8][2] = fbits(base[g * KSTR + t + 4]);
        qf[k8][3] = fbits(base[(g + 8) * KSTR + t + 4]);
    }

    float of[8][4];
    #pragma unroll
    for (int nt = 0; nt < 8; nt++)
        #pragma unroll
        for (int e = 0; e < 4; e++) of[nt][e] = 0.0f;

    float mA = -CUDART_INF_F, mB = -CUDART_INF_F;
    float lA = 0.0f, lB = 0.0f;

    const int ktEnd = causal ? qt : (SEQ / 64 - 1);

    for (int kt = 0; kt <= ktEnd; kt++) {
        __syncthreads();   // protect Ks/Vs from previous iteration's readers
        const float* Kt = Kg + (size_t)kt * 64 * DHEAD;
        const float* Vt = Vg + (size_t)kt * 64 * DHEAD;
        for (int i = tid; i < 64 * 16; i += 128) {
            const int r = i >> 4;
            const int c4 = (i & 15) * 4;
            float4 kv = *(const float4*)(Kt + r * 64 + c4);
            float* kp = &Ks[r * KSTR + c4];
            kp[0] = tf32r(kv.x); kp[1] = tf32r(kv.y);
            kp[2] = tf32r(kv.z); kp[3] = tf32r(kv.w);
            float4 vv = *(const float4*)(Vt + r * 64 + c4);
            float* vp = &Vs[r * VSTR + c4];
            vp[0] = tf32r(vv.x); vp[1] = tf32r(vv.y);
            vp[2] = tf32r(vv.z); vp[3] = tf32r(vv.w);
        }
        __syncthreads();

        // ---- S = (Q/8) K^T : m16 x n64, k=64 ----
        float sf[8][4];
        #pragma unroll
        for (int nt = 0; nt < 8; nt++)
            #pragma unroll
            for (int e = 0; e < 4; e++) sf[nt][e] = 0.0f;

        #pragma unroll
        for (int k8 = 0; k8 < 8; k8++) {
            #pragma unroll
            for (int nt = 0; nt < 8; nt++) {
                const float* bb = &Ks[(nt * 8 + g) * KSTR + k8 * 8];
                mma_tf32(sf[nt], qf[k8][0], qf[k8][1], qf[k8][2], qf[k8][3],
                         fbits(bb[t]), fbits(bb[t + 4]));
            }
        }

        // ---- causal mask on the diagonal tile ----
        if (causal && kt == qt) {
            #pragma unroll
            for (int nt = 0; nt < 8; nt++) {
                #pragma unroll
                for (int e = 0; e < 4; e++) {
                    const int col = nt * 8 + 2 * t + (e & 1);
                    const int row = w * 16 + g + ((e >> 1) << 3);
                    if (col > row) sf[nt][e] = -CUDART_INF_F;
                }
            }
        }

        // ---- online softmax (rows: A = g, B = g+8) ----
        float mxA = -CUDART_INF_F, mxB = -CUDART_INF_F;
        #pragma unroll
        for (int nt = 0; nt < 8; nt++) {
            mxA = fmaxf(mxA, fmaxf(sf[nt][0], sf[nt][1]));
            mxB = fmaxf(mxB, fmaxf(sf[nt][2], sf[nt][3]));
        }
        mxA = fmaxf(mxA, __shfl_xor_sync(0xffffffffu, mxA, 1));
        mxA = fmaxf(mxA, __shfl_xor_sync(0xffffffffu, mxA, 2));
        mxB = fmaxf(mxB, __shfl_xor_sync(0xffffffffu, mxB, 1));
        mxB = fmaxf(mxB, __shfl_xor_sync(0xffffffffu, mxB, 2));

        const float mnA = fmaxf(mA, mxA);
        const float mnB = fmaxf(mB, mxB);
        const float aA = __expf(mA - mnA);
        const float aB = __expf(mB - mnB);
        float sA = 0.0f, sB = 0.0f;
        #pragma unroll
        for (int nt = 0; nt < 8; nt++) {
            sf[nt][0] = __expf(sf[nt][0] - mnA);
            sf[nt][1] = __expf(sf[nt][1] - mnA);
            sf[nt][2] = __expf(sf[nt][2] - mnB);
            sf[nt][3] = __expf(sf[nt][3] - mnB);
            sA += sf[nt][0] + sf[nt][1];
            sB += sf[nt][2] + sf[nt][3];
        }
        sA += __shfl_xor_sync(0xffffffffu, sA, 1);
        sA += __shfl_xor_sync(0xffffffffu, sA, 2);
        sB += __shfl_xor_sync(0xffffffffu, sB, 1);
        sB += __shfl_xor_sync(0xffffffffu, sB, 2);
        lA = lA * aA + sA;
        lB = lB * aB + sB;
        mA = mnA;
        mB = mnB;
        #pragma unroll
        for (int nt = 0; nt < 8; nt++) {
            of[nt][0] *= aA; of[nt][1] *= aA;
            of[nt][2] *= aB; of[nt][3] *= aB;
        }

        // ---- write P (per-warp-private rows), reload as A fragments ----
        #pragma unroll
        for (int nt = 0; nt < 8; nt++) {
            const int c = nt * 8 + 2 * t;
            float* p0 = &Ps[(w * 16 + g) * KSTR + c];
            float* p1 = &Ps[(w * 16 + g + 8) * KSTR + c];
            p0[0] = tf32r(sf[nt][0]); p0[1] = tf32r(sf[nt][1]);
            p1[0] = tf32r(sf[nt][2]); p1[1] = tf32r(sf[nt][3]);
        }
        __syncwarp();

        // ---- O += P V : m16 x n64, k=64 (B frag reads V row-major) ----
        #pragma unroll
        for (int k8 = 0; k8 < 8; k8++) {
            const float* base = &Ps[(w * 16) * KSTR + k8 * 8];
            const uint32_t a0 = fbits(base[g * KSTR + t]);
            const uint32_t a1 = fbits(base[(g + 8) * KSTR + t]);
            const uint32_t a2 = fbits(base[g * KSTR + t + 4]);
            const uint32_t a3 = fbits(base[(g + 8) * KSTR + t + 4]);
            #pragma unroll
            for (int nt = 0; nt < 8; nt++) {
                const uint32_t b0 = fbits(Vs[(k8 * 8 + t) * VSTR + nt * 8 + g]);
                const uint32_t b1 = fbits(Vs[(k8 * 8 + t + 4) * VSTR + nt * 8 + g]);
                mma_tf32(of[nt], a0, a1, a2, a3, b0, b1);
            }
        }
    }

    // ---- epilogue: normalize, store to g_attn [b, s, h*64+d] ----
    const float iA = 1.0f / lA;
    const float iB = 1.0f / lB;
    const int qrow = qt * 64 + w * 16;
    #pragma unroll
    for (int nt = 0; nt < 8; nt++) {
        const int d = h * 64 + nt * 8 + 2 * t;
        float2 v0, v1;
        v0.x = of[nt][0] * iA; v0.y = of[nt][1] * iA;
        v1.x = of[nt][2] * iB; v1.y = of[nt][3] * iB;
        *(float2*)(g_attn + ((size_t)b * SEQ + qrow + g) * DMODEL + d) = v0;
        *(float2*)(g_attn + ((size_t)b * SEQ + qrow + g + 8) * DMODEL + d) = v1;
    }
}

// ---------------------------------------------------------------------------
extern "C" void kernel_launch(void* const* d_in, const int* in_sizes, int n_in,
                              void* d_out, int out_size)
{
    const float* x   = (const float*)d_in[0];   // [4, 2048, 1024]
    const float* w1  = (const float*)d_in[1];   // [3072, 1024]
    const float* b1  = (const float*)d_in[2];   // [3072]
    const float* w2  = (const float*)d_in[3];   // [1024, 1024]
    const float* b2  = (const float*)d_in[4];   // [1024]
    const int*   msk = (const int*)  d_in[5];   // causal flag
    float* out = (float*)d_out;

    const int M = BATCH * SEQ;   // 8192

    // 1) QKV projection (mma.sync tf32) -> g_q/g_k/g_v
    gemm_mma<0><<<dim3(3 * DMODEL / 128, M / 128), 256>>>(
        x, w1, b1, nullptr, M, 3 * DMODEL, DMODEL);

    // 2) Flash attention (mma.sync tf32) -> g_attn
    cudaFuncSetAttribute(flash_mma,
                         cudaFuncAttributeMaxDynamicSharedMemorySize, FLASH_SMEM);
    flash_mma<<<dim3(SEQ / 64, NHEADS, BATCH), 128, FLASH_SMEM>>>(msk);

    // 3) Output projection (mma.sync tf32) -> d_out
    gemm_mma<1><<<dim3(DMODEL / 128, M / 128), 256>>>(
        nullptr, w2, b2, out, M, DMODEL, DMODEL);
}